// round 10
// baseline (speedup 1.0000x reference)
#include <cuda_runtime.h>
#include <cuda_bf16.h>
#include <cstdint>

// Problem shape (fixed): T=32, B=256, C_in=C_out=4096.
#define T_STEPS 32
#define BATCH   256
#define C_IN    4096
#define C_OUT   4096
#define M_DIM   (T_STEPS * BATCH)   // 8192 GEMM rows

// ---------------------------------------------------------------------------
// Device-global scratch.
// ---------------------------------------------------------------------------
__device__ float  g_current[(size_t)M_DIM * C_OUT];          // 128 MB
__device__ int8_t g_a[4][(size_t)M_DIM * C_IN];              // 4 x 32 MB digit planes
__device__ int8_t g_w[4][(size_t)C_OUT * C_IN];              // 4 x 16 MB
__device__ float  g_sa[M_DIM], g_ia[M_DIM];                  // row scales (pow2)
__device__ float  g_sw[C_OUT], g_iw[C_OUT];

// ---------------------------------------------------------------------------
// PTX helpers (baseline sm_80-class: IMMA / ldmatrix / cp.async).
// ---------------------------------------------------------------------------
__device__ __forceinline__ uint32_t smem_u32(const void* p) {
    uint32_t a;
    asm("{ .reg .u64 t; cvta.to.shared.u64 t, %1; cvt.u32.u64 %0, t; }"
        : "=r"(a) : "l"(p));
    return a;
}
// Exact int8 MMA: D(s32) += A(s8,16x32) * B(s8,8x32)^T
__device__ __forceinline__ void imma16832(int* d, const uint32_t* a,
                                          const uint32_t* b) {
    asm volatile(
        "mma.sync.aligned.m16n8k32.row.col.s32.s8.s8.s32 "
        "{%0,%1,%2,%3}, {%4,%5,%6,%7}, {%8,%9}, {%0,%1,%2,%3};"
        : "+r"(d[0]), "+r"(d[1]), "+r"(d[2]), "+r"(d[3])
        : "r"(a[0]), "r"(a[1]), "r"(a[2]), "r"(a[3]), "r"(b[0]), "r"(b[1]));
}
__device__ __forceinline__ void ldsm_x4(uint32_t* r, uint32_t addr) {
    asm volatile("ldmatrix.sync.aligned.m8n8.x4.shared.b16 {%0,%1,%2,%3}, [%4];"
                 : "=r"(r[0]), "=r"(r[1]), "=r"(r[2]), "=r"(r[3]) : "r"(addr));
}
__device__ __forceinline__ void ldsm_x2(uint32_t* r, uint32_t addr) {
    asm volatile("ldmatrix.sync.aligned.m8n8.x2.shared.b16 {%0,%1}, [%2];"
                 : "=r"(r[0]), "=r"(r[1]) : "r"(addr));
}
#define CP_ASYNC16(dst, src)                                                  \
    asm volatile("cp.async.cg.shared.global [%0], [%1], 16;"                  \
                 :: "r"(dst), "l"(src))
#define CP_ASYNC_COMMIT() asm volatile("cp.async.commit_group;" ::: "memory")

// ---------------------------------------------------------------------------
// Row scale: S = 2^(ilogb(max|row|)+1)  (so |x|/S in [0,1)), inv = 1/S.
// Powers of two -> all scalings exact.
// ---------------------------------------------------------------------------
__global__ __launch_bounds__(256)
void rowscale_kernel(const float* __restrict__ src, float* __restrict__ s,
                     float* __restrict__ inv)
{
    const int row = blockIdx.x;
    const float4* p = reinterpret_cast<const float4*>(src + (size_t)row * C_IN);
    float m = 0.0f;
    for (int i = threadIdx.x; i < C_IN / 4; i += 256) {
        const float4 v = p[i];
        m = fmaxf(m, fmaxf(fmaxf(fabsf(v.x), fabsf(v.y)),
                           fmaxf(fabsf(v.z), fabsf(v.w))));
    }
    __shared__ float red[256];
    red[threadIdx.x] = m;
    __syncthreads();
    for (int o = 128; o > 0; o >>= 1) {
        if (threadIdx.x < o)
            red[threadIdx.x] = fmaxf(red[threadIdx.x], red[threadIdx.x + o]);
        __syncthreads();
    }
    if (threadIdx.x == 0) {
        const float mx = red[0];
        int e = 0;
        if (mx > 1e-30f)
            e = (int)((__float_as_uint(mx) >> 23) & 0xFF) - 127;
        s[row]   = __uint_as_float((uint32_t)(e + 1 + 127) << 23);
        inv[row] = __uint_as_float((uint32_t)(127 - (e + 1)) << 23);
    }
}

// ---------------------------------------------------------------------------
// Digit slice: u = x*inv (exact), u = d0*2^-6 + d1*2^-13 + d2*2^-20 + d3*2^-27
// + r (|r|<=2^-28). Digits |d|<=64 fit int8; residual extraction is exact.
// ---------------------------------------------------------------------------
__global__ __launch_bounds__(256)
void slice_kernel(const float* __restrict__ src,
                  int8_t* __restrict__ p0, int8_t* __restrict__ p1,
                  int8_t* __restrict__ p2, int8_t* __restrict__ p3,
                  const float* __restrict__ inv, size_t n4)
{
    const size_t i = (size_t)blockIdx.x * 256 + threadIdx.x;
    if (i >= n4) return;
    const float iv = inv[i >> 10];            // 1024 float4 per 4096-wide row
    const float4 v = reinterpret_cast<const float4*>(src)[i];
    float u[4] = {__fmul_rn(v.x, iv), __fmul_rn(v.y, iv),
                  __fmul_rn(v.z, iv), __fmul_rn(v.w, iv)};
    signed char q0[4], q1[4], q2[4], q3[4];
#pragma unroll
    for (int j = 0; j < 4; j++) {
        float x = u[j];
        const float f0 = rintf(x * 64.0f);      x = fmaf(f0, -0x1p-6f,  x);
        const float f1 = rintf(x * 0x1p13f);    x = fmaf(f1, -0x1p-13f, x);
        const float f2 = rintf(x * 0x1p20f);    x = fmaf(f2, -0x1p-20f, x);
        const float f3 = rintf(x * 0x1p27f);
        q0[j] = (signed char)(int)f0;  q1[j] = (signed char)(int)f1;
        q2[j] = (signed char)(int)f2;  q3[j] = (signed char)(int)f3;
    }
    reinterpret_cast<char4*>(p0)[i] = make_char4(q0[0], q0[1], q0[2], q0[3]);
    reinterpret_cast<char4*>(p1)[i] = make_char4(q1[0], q1[1], q1[2], q1[3]);
    reinterpret_cast<char4*>(p2)[i] = make_char4(q2[0], q2[1], q2[2], q2[3]);
    reinterpret_cast<char4*>(p3)[i] = make_char4(q3[0], q3[1], q3[2], q3[3]);
}

// ---------------------------------------------------------------------------
// Ozaki int8 GEMM: C[m][n] = Sa[m]*Sw[n]*2^-40*V + bias[n],
//   V = sum_{i+j<=4} Wij * 2^{7*(4-i-j)},  Wij = exact int32 digit dots.
// Tile BM=128, BN=64, BK=32; 8 warps (4M x 2N), warp tile 32x32.
// 13 IMMA products/slab chained exactly in 5 int32 groups across all of K.
// ---------------------------------------------------------------------------
#define BK       32
#define NSLAB    (C_IN / BK)          // 128
#define ROWB     48                   // 32 data bytes + 16 pad (conflict-free)
#define A_SLICE  (128 * ROWB)         // 6144
#define B_SLICE  (64 * ROWB)          // 3072
#define A_REGION (4 * A_SLICE)        // 24576
#define STAGE_B  (A_REGION + 4 * B_SLICE)  // 36864
#define SMEM_BYTES (2 * STAGE_B)           // 73728

__global__ __launch_bounds__(256, 1)
void gemm_i8_ozaki_kernel(const float* __restrict__ bias,
                          float* __restrict__ C)
{
    extern __shared__ char smem[];
    const uint32_t sb = smem_u32(smem);

    const int tid   = threadIdx.x;
    const int wid   = tid >> 5;
    const int lane  = tid & 31;
    const int warpM = wid & 3;
    const int warpN = wid >> 2;

    // Supertile raster 8x8 over (64 mt x 64 nt).
    const int bid = blockIdx.x;
    const int sup = bid >> 6;
    const int mt  = (sup >> 3) * 8 + ((bid >> 3) & 7);
    const int nt  = (sup & 7) * 8 + (bid & 7);
    const int m0  = mt * 128;
    const int n0  = nt * 64;

    // Per-thread cp.async plan. A: 1024 16B chunks (4/thread), B: 512 (2/thread).
    const int8_t* srcA[4]; uint32_t dstA[4];
#pragma unroll
    for (int c = 0; c < 4; c++) {
        const int q = tid + 256 * c;
        const int sp = q >> 8, rem = q & 255, r = rem >> 1, ch = rem & 1;
        srcA[c] = &g_a[sp][(size_t)(m0 + r) * C_IN + ch * 16];
        dstA[c] = sp * A_SLICE + r * ROWB + ch * 16;
    }
    const int8_t* srcB[2]; uint32_t dstB[2];
#pragma unroll
    for (int c = 0; c < 2; c++) {
        const int q = tid + 256 * c;
        const int sp = q >> 7, rem = q & 127, r = rem >> 1, ch = rem & 1;
        srcB[c] = &g_w[sp][(size_t)(n0 + r) * C_IN + ch * 16];
        dstB[c] = A_REGION + sp * B_SLICE + r * ROWB + ch * 16;
    }

    // ldmatrix lane addressing (canonical m16n8k32 s8 fragment layout).
    const uint32_t aoff = (uint32_t)((warpM * 32 + (lane & 15)) * ROWB +
                                     ((lane & 16) ? 16 : 0));
    const uint32_t boff = (uint32_t)(A_REGION +
                                     (warpN * 32 + (lane & 7)) * ROWB +
                                     ((lane & 8) ? 16 : 0));

    // 5 exact int32 accumulator groups (weights 2^{7*(4-g)}, g=0..4).
    int acc[5][2][4][4];
#pragma unroll
    for (int g = 0; g < 5; g++)
#pragma unroll
        for (int mb = 0; mb < 2; mb++)
#pragma unroll
            for (int nb = 0; nb < 4; nb++)
#pragma unroll
                for (int e = 0; e < 4; e++) acc[g][mb][nb][e] = 0;

    // Prologue: stage slab 0.
    {
#pragma unroll
        for (int c = 0; c < 4; c++) CP_ASYNC16(sb + dstA[c], srcA[c]);
#pragma unroll
        for (int c = 0; c < 2; c++) CP_ASYNC16(sb + dstB[c], srcB[c]);
        CP_ASYNC_COMMIT();
    }

    for (int s = 0; s < NSLAB; s++) {
        if (s + 1 < NSLAB) {
            const uint32_t st = sb + ((s + 1) & 1) * STAGE_B;
            const int k1 = (s + 1) * BK;
#pragma unroll
            for (int c = 0; c < 4; c++) CP_ASYNC16(st + dstA[c], srcA[c] + k1);
#pragma unroll
            for (int c = 0; c < 2; c++) CP_ASYNC16(st + dstB[c], srcB[c] + k1);
            CP_ASYNC_COMMIT();
            asm volatile("cp.async.wait_group 1;" ::: "memory");
        } else {
            asm volatile("cp.async.wait_group 0;" ::: "memory");
        }
        __syncthreads();

        const uint32_t stb = sb + (s & 1) * STAGE_B;

        // B fragments: all 4 digit slices resident (32 regs).
        uint32_t Bf[4][4][2];
#pragma unroll
        for (int j = 0; j < 4; j++)
#pragma unroll
            for (int nb = 0; nb < 4; nb++)
                ldsm_x2(Bf[j][nb], stb + boff + j * B_SLICE + nb * 8 * ROWB);

        // A slices on demand; 13 exact IMMA products into 5 groups.
#pragma unroll
        for (int i = 0; i < 4; i++) {
            uint32_t Af[2][4];
#pragma unroll
            for (int mb = 0; mb < 2; mb++)
                ldsm_x4(Af[mb], stb + i * A_SLICE + aoff + mb * 16 * ROWB);
#pragma unroll
            for (int j = 0; j < 4; j++) {
                if (i + j <= 4) {
#pragma unroll
                    for (int mb = 0; mb < 2; mb++)
#pragma unroll
                        for (int nb = 0; nb < 4; nb++)
                            imma16832(acc[i + j][mb][nb], Af[mb], Bf[j][nb]);
                }
            }
        }
        __syncthreads();
    }

    // Epilogue: exact int64 Horner combine, fp64 scale+bias, one fp32 rounding.
    const int g4  = lane >> 2;
    const int tc  = (lane & 3) * 2;
#pragma unroll
    for (int mb = 0; mb < 2; mb++)
#pragma unroll
        for (int nb = 0; nb < 4; nb++) {
            const int row = m0 + warpM * 32 + mb * 16 + g4;
            const int col = n0 + warpN * 32 + nb * 8 + tc;
            const double sr0 = (double)g_sa[row];
            const double sr1 = (double)g_sa[row + 8];
            const double sc0 = (double)g_sw[col]     * 0x1p-40;
            const double sc1 = (double)g_sw[col + 1] * 0x1p-40;
            const double b0  = (double)bias[col];
            const double b1  = (double)bias[col + 1];

            float o[4];
#pragma unroll
            for (int e = 0; e < 4; e++) {
                long long V = acc[0][mb][nb][e];
#pragma unroll
                for (int g = 1; g < 5; g++)
                    V = V * 128 + (long long)acc[g][mb][nb][e];
                const double sr = (e < 2) ? sr0 : sr1;
                const double sc = (e & 1) ? sc1 : sc0;
                const double bb = (e & 1) ? b1 : b0;
                o[e] = (float)(fma((double)V, sr * sc, bb));
            }
            *reinterpret_cast<float2*>(C + (size_t)row * C_OUT + col) =
                make_float2(o[0], o[1]);
            *reinterpret_cast<float2*>(C + (size_t)(row + 8) * C_OUT + col) =
                make_float2(o[2], o[3]);
        }
}

// ---------------------------------------------------------------------------
// LIF scan (identical numerics to the passing R5 kernel).
// ---------------------------------------------------------------------------
__global__ __launch_bounds__(256)
void lif_scan_kernel(const float* __restrict__ cur,
                     float* __restrict__ out,
                     const float* __restrict__ decay,
                     const float* __restrict__ thresh)
{
    const int i = blockIdx.x * blockDim.x + threadIdx.x;
    const float d  = decay[0];
    const float th = thresh[0];
    const size_t stride = (size_t)BATCH * C_OUT;

    float mem = 0.0f;
#pragma unroll
    for (int t = 0; t < T_STEPS; t++) {
        const size_t idx = (size_t)t * stride + i;
        const float c = cur[idx];
        mem = __fadd_rn(__fmul_rn(d, mem), c);
        const float v = __fsub_rn(mem, th);
        const float s = (v > 0.0f) ? 1.0f : 0.0f;
        out[idx] = s;
        mem = __fsub_rn(mem, __fmul_rn(s, th));
    }
}

// ---------------------------------------------------------------------------
// Launch: inputs in metadata order: x, W, b, decay, thresh.
// ---------------------------------------------------------------------------
extern "C" void kernel_launch(void* const* d_in, const int* in_sizes, int n_in,
                              void* d_out, int out_size)
{
    const float* x      = (const float*)d_in[0];  // [T, B, C_IN]
    const float* W      = (const float*)d_in[1];  // [C_OUT, C_IN]
    const float* bias   = (const float*)d_in[2];  // [C_OUT]
    const float* decay  = (const float*)d_in[3];  // [1]
    const float* thresh = (const float*)d_in[4];  // [1]
    float* out = (float*)d_out;                   // [T, B, C_OUT]

    float *cur, *sa, *ia, *sw, *iw;
    int8_t *pa, *pw;
    cudaGetSymbolAddress((void**)&cur, g_current);
    cudaGetSymbolAddress((void**)&pa,  g_a);
    cudaGetSymbolAddress((void**)&pw,  g_w);
    cudaGetSymbolAddress((void**)&sa,  g_sa);
    cudaGetSymbolAddress((void**)&ia,  g_ia);
    cudaGetSymbolAddress((void**)&sw,  g_sw);
    cudaGetSymbolAddress((void**)&iw,  g_iw);
    const size_t aplane = (size_t)M_DIM * C_IN;
    const size_t wplane = (size_t)C_OUT * C_IN;

    cudaFuncSetAttribute(gemm_i8_ozaki_kernel,
                         cudaFuncAttributeMaxDynamicSharedMemorySize, SMEM_BYTES);

    // 1) row scales (exact powers of two)
    rowscale_kernel<<<M_DIM, 256>>>(x, sa, ia);
    rowscale_kernel<<<C_OUT, 256>>>(W, sw, iw);

    // 2) exact 4-digit int8 slicing
    const size_t nA4 = aplane / 4, nB4 = wplane / 4;
    slice_kernel<<<(unsigned)((nA4 + 255) / 256), 256>>>(
        x, pa, pa + aplane, pa + 2 * aplane, pa + 3 * aplane, ia, nA4);
    slice_kernel<<<(unsigned)((nB4 + 255) / 256), 256>>>(
        W, pw, pw + wplane, pw + 2 * wplane, pw + 3 * wplane, iw, nB4);

    // 3) exact int8 tensor-core GEMM -> currents
    gemm_i8_ozaki_kernel<<<4096, 256, SMEM_BYTES>>>(bias, cur);

    // 4) LIF temporal scan
    const int neurons = BATCH * C_OUT;
    lif_scan_kernel<<<neurons / 256, 256>>>(cur, out, decay, thresh);
}

// round 12
// speedup vs baseline: 1.9837x; 1.9837x over previous
#include <cuda_runtime.h>
#include <cstdint>

// Problem shape (fixed by setup_inputs): T=32, B=256, C_in=C_out=4096.
#define T_STEPS 32
#define BATCH   256
#define C_IN    4096
#define C_OUT   4096
#define M_DIM   (T_STEPS * BATCH)   // 8192 GEMM rows

// Scratch for pre-activation currents: [T*B, C_OUT] fp32 = 128 MB.
__device__ float g_current[(size_t)M_DIM * C_OUT];

typedef unsigned long long ull;

// Packed f32x2 ops. Per-component rounding identical to scalar RN ops.
__device__ __forceinline__ ull fma2(ull a, ull b, ull c) {
    ull d;
    asm("fma.rn.f32x2 %0, %1, %2, %3;" : "=l"(d) : "l"(a), "l"(b), "l"(c));
    return d;
}
__device__ __forceinline__ ull add2(ull a, ull b) {
    ull d;
    asm("add.rn.f32x2 %0, %1, %2;" : "=l"(d) : "l"(a), "l"(b));
    return d;
}
__device__ __forceinline__ ull pack2(float lo, float hi) {
    ull d;
    asm("mov.b64 %0, {%1, %2};" : "=l"(d) : "f"(lo), "f"(hi));
    return d;
}
__device__ __forceinline__ void unpack2(ull v, float& lo, float& hi) {
    asm("mov.b64 {%0, %1}, %2;" : "=f"(lo), "=f"(hi) : "l"(v));
}

// ---------------------------------------------------------------------------
// GEMM (NT): C[m][n] = sum_k A[m][k]*W[n][k] + bias[n]
// Tile 128x64x32 (BK=32 — the numerics-validated slab size), 256 threads,
// 8x4 micro-tile, f32x2-packed accumulators.
// vs R6 (7712us, PASS @ 9.680577e-4): the ONLY change is that B is stored
// PRE-DUPLICATED in SMEM as f32x2 pairs, so the inner loop has zero packing
// MOVs competing with FFMA2 on the issue pipe. Arithmetic sequence per output
// element is bit-identical to R6: fresh blk per 32-K slab (RN-exact packed
// FMA chain) + packed Kahan merge into (acc, cmp).
// ---------------------------------------------------------------------------
#define BM 128
#define BN 64
#define BK 32
#define TM 8
#define TN 4

// Dynamic SMEM layout:
//   As  [2][BK][BM]  floats : 2*32*128*4 = 32768 B
//   Bsd [2][BK][BN]  ull    : 2*32*64*8  = 32768 B   (duplicated pairs)
#define AS_WORDS   (BK * BM)           // per buffer, in floats
#define BS_PAIRS   (BK * BN)           // per buffer, in ull
#define SMEM_BYTES (2 * AS_WORDS * 4 + 2 * BS_PAIRS * 8)   // 65536

__global__ __launch_bounds__(256, 1)
void gemm_nt_bias_kahan_f32x2_kernel(const float* __restrict__ A,
                                     const float* __restrict__ W,
                                     const float* __restrict__ bias,
                                     float* __restrict__ C)
{
    extern __shared__ char smem[];
    float* As  = reinterpret_cast<float*>(smem);                  // [2][BK][BM]
    ull*   Bsd = reinterpret_cast<ull*>(smem + 2 * AS_WORDS * 4); // [2][BK][BN]

    const int K  = C_IN;
    const int m0 = blockIdx.y * BM;
    const int n0 = blockIdx.x * BN;

    const int tid = threadIdx.x;
    const int tx  = tid & 15;      // 16 thread-cols * TN=4  -> 64
    const int ty  = tid >> 4;      // 16 thread-rows * TM=8  -> 128

    // Packed accumulators: [pair-of-m][n], pair ip covers rows (2ip, 2ip+1).
    ull acc[TM / 2][TN];
    ull cmp[TM / 2][TN];
#pragma unroll
    for (int ip = 0; ip < TM / 2; ip++)
#pragma unroll
        for (int j = 0; j < TN; j++) { acc[ip][j] = 0ull; cmp[ip][j] = 0ull; }

    const ull negone = pack2(-1.0f, -1.0f);

    // Register staging for global->shared prefetch.
    // A slab: 128 rows x 32 k = 1024 float4 -> 4/thread.
    // B slab:  64 rows x 32 k =  512 float4 -> 2/thread.
    float4 rA[4], rB[2];

    auto ldg_slab = [&](int k0) {
#pragma unroll
        for (int i = 0; i < 4; i++) {
            const int s   = i * 256 + tid;
            const int row = s >> 3;       // 8 float4-chunks per row
            const int q   = s & 7;
            rA[i] = *reinterpret_cast<const float4*>(
                A + (size_t)(m0 + row) * K + k0 + q * 4);
        }
#pragma unroll
        for (int i = 0; i < 2; i++) {
            const int s   = i * 256 + tid;
            const int row = s >> 3;
            const int q   = s & 7;
            rB[i] = *reinterpret_cast<const float4*>(
                W + (size_t)(n0 + row) * K + k0 + q * 4);
        }
    };
    auto sts_slab = [&](int buf) {
        float* Ab = As + buf * AS_WORDS;
#pragma unroll
        for (int i = 0; i < 4; i++) {
            const int s   = i * 256 + tid;
            const int row = s >> 3;
            const int q   = s & 7;
            Ab[(q * 4 + 0) * BM + row] = rA[i].x;
            Ab[(q * 4 + 1) * BM + row] = rA[i].y;
            Ab[(q * 4 + 2) * BM + row] = rA[i].z;
            Ab[(q * 4 + 3) * BM + row] = rA[i].w;
        }
        ull* Bb = Bsd + buf * BS_PAIRS;
#pragma unroll
        for (int i = 0; i < 2; i++) {
            const int s   = i * 256 + tid;
            const int row = s >> 3;
            const int q   = s & 7;
            // Pre-duplicate here (load phase) so the inner loop has no MOVs.
            Bb[(q * 4 + 0) * BN + row] = pack2(rB[i].x, rB[i].x);
            Bb[(q * 4 + 1) * BN + row] = pack2(rB[i].y, rB[i].y);
            Bb[(q * 4 + 2) * BN + row] = pack2(rB[i].z, rB[i].z);
            Bb[(q * 4 + 3) * BN + row] = pack2(rB[i].w, rB[i].w);
        }
    };

    // Prologue: stage slab 0.
    ldg_slab(0);
    sts_slab(0);
    __syncthreads();

    int buf = 0;
    for (int k0 = 0; k0 < K; k0 += BK) {
        const bool has_next = (k0 + BK) < K;
        if (has_next) ldg_slab(k0 + BK);   // prefetch next slab into registers

        // Fresh packed slab accumulator.
        ull blk[TM / 2][TN];
#pragma unroll
        for (int ip = 0; ip < TM / 2; ip++)
#pragma unroll
            for (int j = 0; j < TN; j++) blk[ip][j] = 0ull;

        const float* Ab = As + buf * AS_WORDS;
        const ull*   Bb = Bsd + buf * BS_PAIRS;

#pragma unroll
        for (int kk = 0; kk < BK; kk++) {
            // A fragment: rows ty*8 .. ty*8+7 as 4 natural f32x2 pairs.
            const ulonglong2 av0 =
                *reinterpret_cast<const ulonglong2*>(Ab + kk * BM + ty * TM);
            const ulonglong2 av1 =
                *reinterpret_cast<const ulonglong2*>(Ab + kk * BM + ty * TM + 4);
            ull ap[4];
            ap[0] = av0.x; ap[1] = av0.y; ap[2] = av1.x; ap[3] = av1.y;

            // B fragment: 4 pre-duplicated pairs, straight from SMEM.
            const ulonglong2 bv0 =
                *reinterpret_cast<const ulonglong2*>(Bb + kk * BN + tx * TN);
            const ulonglong2 bv1 =
                *reinterpret_cast<const ulonglong2*>(Bb + kk * BN + tx * TN + 2);
            ull bd[4];
            bd[0] = bv0.x; bd[1] = bv0.y; bd[2] = bv1.x; bd[3] = bv1.y;

#pragma unroll
            for (int ip = 0; ip < TM / 2; ip++)
#pragma unroll
                for (int j = 0; j < TN; j++)
                    blk[ip][j] = fma2(ap[ip], bd[j], blk[ip][j]);
        }

        // Packed Kahan merge (component-wise identical to scalar R5):
        //   y = blk - cmp; t = acc + y; cmp = (t - acc) - y; acc = t.
#pragma unroll
        for (int ip = 0; ip < TM / 2; ip++)
#pragma unroll
            for (int j = 0; j < TN; j++) {
                const ull y = fma2(cmp[ip][j], negone, blk[ip][j]); // blk - cmp
                const ull t = add2(acc[ip][j], y);                  // acc + y
                const ull d = fma2(acc[ip][j], negone, t);          // t - acc
                cmp[ip][j]  = fma2(y, negone, d);                   // d - y
                acc[ip][j]  = t;
            }

        if (has_next) {
            sts_slab(buf ^ 1);
            __syncthreads();
            buf ^= 1;
        }
    }

    // Epilogue: fold compensation, add bias, store fp32 (same exprs as R5/R6).
#pragma unroll
    for (int ip = 0; ip < TM / 2; ip++) {
        float a_lo[TN], a_hi[TN], c_lo[TN], c_hi[TN];
#pragma unroll
        for (int j = 0; j < TN; j++) {
            unpack2(acc[ip][j], a_lo[j], a_hi[j]);
            unpack2(cmp[ip][j], c_lo[j], c_hi[j]);
        }
        const int n = n0 + tx * TN;
        {
            const int m = m0 + ty * TM + 2 * ip;
            float4 v;
            v.x = __fadd_rn(__fsub_rn(a_lo[0], c_lo[0]), bias[n + 0]);
            v.y = __fadd_rn(__fsub_rn(a_lo[1], c_lo[1]), bias[n + 1]);
            v.z = __fadd_rn(__fsub_rn(a_lo[2], c_lo[2]), bias[n + 2]);
            v.w = __fadd_rn(__fsub_rn(a_lo[3], c_lo[3]), bias[n + 3]);
            *reinterpret_cast<float4*>(C + (size_t)m * C_OUT + n) = v;
        }
        {
            const int m = m0 + ty * TM + 2 * ip + 1;
            float4 v;
            v.x = __fadd_rn(__fsub_rn(a_hi[0], c_hi[0]), bias[n + 0]);
            v.y = __fadd_rn(__fsub_rn(a_hi[1], c_hi[1]), bias[n + 1]);
            v.z = __fadd_rn(__fsub_rn(a_hi[2], c_hi[2]), bias[n + 2]);
            v.w = __fadd_rn(__fsub_rn(a_hi[3], c_hi[3]), bias[n + 3]);
            *reinterpret_cast<float4*>(C + (size_t)m * C_OUT + n) = v;
        }
    }
}

// ---------------------------------------------------------------------------
// LIF scan (identical numerics and form to the passing R5 kernel).
// ---------------------------------------------------------------------------
__global__ __launch_bounds__(256)
void lif_scan_kernel(const float* __restrict__ cur,
                     float* __restrict__ out,
                     const float* __restrict__ decay,
                     const float* __restrict__ thresh)
{
    const int i = blockIdx.x * blockDim.x + threadIdx.x;
    const float d  = decay[0];
    const float th = thresh[0];
    const size_t stride = (size_t)BATCH * C_OUT;

    float mem = 0.0f;
#pragma unroll
    for (int t = 0; t < T_STEPS; t++) {
        const size_t idx = (size_t)t * stride + i;
        const float c = cur[idx];
        mem = __fadd_rn(__fmul_rn(d, mem), c);
        const float v = __fsub_rn(mem, th);
        const float s = (v > 0.0f) ? 1.0f : 0.0f;
        out[idx] = s;
        mem = __fsub_rn(mem, __fmul_rn(s, th));
    }
}

// ---------------------------------------------------------------------------
// Launch: inputs in metadata order: x, W, b, decay, thresh.
// ---------------------------------------------------------------------------
extern "C" void kernel_launch(void* const* d_in, const int* in_sizes, int n_in,
                              void* d_out, int out_size)
{
    const float* x      = (const float*)d_in[0];  // [T, B, C_IN]
    const float* W      = (const float*)d_in[1];  // [C_OUT, C_IN]
    const float* bias   = (const float*)d_in[2];  // [C_OUT]
    const float* decay  = (const float*)d_in[3];  // [1]
    const float* thresh = (const float*)d_in[4];  // [1]
    float* out = (float*)d_out;                   // [T, B, C_OUT]

    float* cur = nullptr;
    cudaGetSymbolAddress((void**)&cur, g_current);

    cudaFuncSetAttribute(gemm_nt_bias_kahan_f32x2_kernel,
                         cudaFuncAttributeMaxDynamicSharedMemorySize,
                         SMEM_BYTES);

    dim3 gblock(256);
    dim3 ggrid(C_OUT / BN, M_DIM / BM);   // (64, 64)
    gemm_nt_bias_kahan_f32x2_kernel<<<ggrid, gblock, SMEM_BYTES>>>(x, W, bias,
                                                                   cur);

    const int neurons = BATCH * C_OUT;    // 1,048,576
    lif_scan_kernel<<<neurons / 256, 256>>>(cur, out, decay, thresh);
}

// round 13
// speedup vs baseline: 3.4116x; 1.7198x over previous
#include <cuda_runtime.h>
#include <cstdint>

// Problem shape (fixed by setup_inputs): T=32, B=256, C_in=C_out=4096.
#define T_STEPS 32
#define BATCH   256
#define C_IN    4096
#define C_OUT   4096
#define M_DIM   (T_STEPS * BATCH)   // 8192 GEMM rows

// Scratch for pre-activation currents: [T*B, C_OUT] fp32 = 128 MB.
__device__ float g_current[(size_t)M_DIM * C_OUT];

typedef unsigned long long ull;

// Packed f32x2 ops. Per-component rounding identical to scalar RN ops.
__device__ __forceinline__ ull fma2(ull a, ull b, ull c) {
    ull d;
    asm("fma.rn.f32x2 %0, %1, %2, %3;" : "=l"(d) : "l"(a), "l"(b), "l"(c));
    return d;
}
__device__ __forceinline__ ull add2(ull a, ull b) {
    ull d;
    asm("add.rn.f32x2 %0, %1, %2;" : "=l"(d) : "l"(a), "l"(b));
    return d;
}
__device__ __forceinline__ ull pack2(float lo, float hi) {
    ull d;
    asm("mov.b64 %0, {%1, %2};" : "=l"(d) : "f"(lo), "f"(hi));
    return d;
}
__device__ __forceinline__ void unpack2(ull v, float& lo, float& hi) {
    asm("mov.b64 {%0, %1}, %2;" : "=f"(lo), "=f"(hi) : "l"(v));
}

// ---------------------------------------------------------------------------
// GEMM (NT): C[m][n] = sum_k A[m][k]*W[n][k] + bias[n]
// Structure identical to the R6 kernel (7712us PASS) EXCEPT the slab merge:
//   R6:  Kahan merge (4 packed ops/accumulator/slab) = 12.5% fma-pipe tax
//   now: plain add2 (1 op/accumulator/slab)          =  3.1% tax
// Numerics: fresh 32-term packed-FMA chains per slab (unchanged, the proven
// delta <= 1e-6 config) + a 128-term plain merge chain (error ~sqrt(128)*
// eps*|C| ~ 0.7e-6, inside the calibrated 2.5e-6 flip budget).
// fma-pipe-bound: MOVs/LDS/issue are hidden (proven by the R6-vs-R12 A/B).
// ---------------------------------------------------------------------------
#define BM 128
#define BN 64
#define BK 32
#define TM 8
#define TN 4

__global__ __launch_bounds__(256, 1)
void gemm_nt_bias_f32x2_kernel(const float* __restrict__ A,
                               const float* __restrict__ W,
                               const float* __restrict__ bias,
                               float* __restrict__ C)
{
    __shared__ float As[2][BK][BM];   // 2 x 16 KB
    __shared__ float Bs[2][BK][BN];   // 2 x  8 KB

    const int K  = C_IN;
    const int m0 = blockIdx.y * BM;
    const int n0 = blockIdx.x * BN;

    const int tid = threadIdx.x;
    const int tx  = tid & 15;      // 16 thread-cols * TN=4  -> 64
    const int ty  = tid >> 4;      // 16 thread-rows * TM=8  -> 128

    // Packed accumulators: [pair-of-m][n], pair ip covers rows (2ip, 2ip+1).
    ull acc[TM / 2][TN];
#pragma unroll
    for (int ip = 0; ip < TM / 2; ip++)
#pragma unroll
        for (int j = 0; j < TN; j++) acc[ip][j] = 0ull;

    // Register staging for global->shared prefetch (same slot plan as R6).
    float4 rA[4], rB[2];

    auto ldg_slab = [&](int k0) {
#pragma unroll
        for (int i = 0; i < 4; i++) {
            const int s   = tid * 4 + i;
            const int row = s >> 3;
            const int q   = s & 7;
            rA[i] = *reinterpret_cast<const float4*>(
                A + (size_t)(m0 + row) * K + k0 + q * 4);
        }
#pragma unroll
        for (int i = 0; i < 2; i++) {
            const int s   = tid * 2 + i;
            const int row = s >> 3;
            const int q   = s & 7;
            rB[i] = *reinterpret_cast<const float4*>(
                W + (size_t)(n0 + row) * K + k0 + q * 4);
        }
    };
    auto sts_slab = [&](int buf) {
#pragma unroll
        for (int i = 0; i < 4; i++) {
            const int s   = tid * 4 + i;
            const int row = s >> 3;
            const int q   = s & 7;
            As[buf][q * 4 + 0][row] = rA[i].x;
            As[buf][q * 4 + 1][row] = rA[i].y;
            As[buf][q * 4 + 2][row] = rA[i].z;
            As[buf][q * 4 + 3][row] = rA[i].w;
        }
#pragma unroll
        for (int i = 0; i < 2; i++) {
            const int s   = tid * 2 + i;
            const int row = s >> 3;
            const int q   = s & 7;
            Bs[buf][q * 4 + 0][row] = rB[i].x;
            Bs[buf][q * 4 + 1][row] = rB[i].y;
            Bs[buf][q * 4 + 2][row] = rB[i].z;
            Bs[buf][q * 4 + 3][row] = rB[i].w;
        }
    };

    // Prologue: stage slab 0.
    ldg_slab(0);
    sts_slab(0);
    __syncthreads();

    int buf = 0;
    for (int k0 = 0; k0 < K; k0 += BK) {
        const bool has_next = (k0 + BK) < K;
        if (has_next) ldg_slab(k0 + BK);   // prefetch next slab into registers

        // Fresh packed slab accumulator (32-term RN-exact FMA chains).
        ull blk[TM / 2][TN];
#pragma unroll
        for (int ip = 0; ip < TM / 2; ip++)
#pragma unroll
            for (int j = 0; j < TN; j++) blk[ip][j] = 0ull;

#pragma unroll
        for (int kk = 0; kk < BK; kk++) {
            // A fragment: rows ty*8 .. ty*8+7 as 4 natural f32x2 pairs.
            const ulonglong2 av0 =
                *reinterpret_cast<const ulonglong2*>(&As[buf][kk][ty * TM]);
            const ulonglong2 av1 =
                *reinterpret_cast<const ulonglong2*>(&As[buf][kk][ty * TM + 4]);
            ull ap[4];
            ap[0] = av0.x; ap[1] = av0.y; ap[2] = av1.x; ap[3] = av1.y;

            // B fragment: 4 scalars, duplicated into packed lanes (MOVs are
            // on the non-binding pipe — proven free by the R6/R12 A/B test).
            const float4 bv =
                *reinterpret_cast<const float4*>(&Bs[buf][kk][tx * TN]);
            ull bd[4];
            bd[0] = pack2(bv.x, bv.x);
            bd[1] = pack2(bv.y, bv.y);
            bd[2] = pack2(bv.z, bv.z);
            bd[3] = pack2(bv.w, bv.w);

#pragma unroll
            for (int ip = 0; ip < TM / 2; ip++)
#pragma unroll
                for (int j = 0; j < TN; j++)
                    blk[ip][j] = fma2(ap[ip], bd[j], blk[ip][j]);
        }

        // Plain merge: one packed add per accumulator per slab.
#pragma unroll
        for (int ip = 0; ip < TM / 2; ip++)
#pragma unroll
            for (int j = 0; j < TN; j++)
                acc[ip][j] = add2(acc[ip][j], blk[ip][j]);

        if (has_next) {
            sts_slab(buf ^ 1);   // fill the idle buffer
            __syncthreads();
            buf ^= 1;
        }
    }

    // Epilogue: add bias, store fp32 currents.
#pragma unroll
    for (int ip = 0; ip < TM / 2; ip++) {
        float a_lo[TN], a_hi[TN];
#pragma unroll
        for (int j = 0; j < TN; j++)
            unpack2(acc[ip][j], a_lo[j], a_hi[j]);
        const int n = n0 + tx * TN;
        {
            const int m = m0 + ty * TM + 2 * ip;
            float4 v;
            v.x = __fadd_rn(a_lo[0], bias[n + 0]);
            v.y = __fadd_rn(a_lo[1], bias[n + 1]);
            v.z = __fadd_rn(a_lo[2], bias[n + 2]);
            v.w = __fadd_rn(a_lo[3], bias[n + 3]);
            *reinterpret_cast<float4*>(C + (size_t)m * C_OUT + n) = v;
        }
        {
            const int m = m0 + ty * TM + 2 * ip + 1;
            float4 v;
            v.x = __fadd_rn(a_hi[0], bias[n + 0]);
            v.y = __fadd_rn(a_hi[1], bias[n + 1]);
            v.z = __fadd_rn(a_hi[2], bias[n + 2]);
            v.w = __fadd_rn(a_hi[3], bias[n + 3]);
            *reinterpret_cast<float4*>(C + (size_t)m * C_OUT + n) = v;
        }
    }
}

// ---------------------------------------------------------------------------
// LIF scan (identical numerics and form to the passing R5 kernel, 38.6us).
// ---------------------------------------------------------------------------
__global__ __launch_bounds__(256)
void lif_scan_kernel(const float* __restrict__ cur,
                     float* __restrict__ out,
                     const float* __restrict__ decay,
                     const float* __restrict__ thresh)
{
    const int i = blockIdx.x * blockDim.x + threadIdx.x;
    const float d  = decay[0];
    const float th = thresh[0];
    const size_t stride = (size_t)BATCH * C_OUT;

    float mem = 0.0f;
#pragma unroll
    for (int t = 0; t < T_STEPS; t++) {
        const size_t idx = (size_t)t * stride + i;
        const float c = cur[idx];
        mem = __fadd_rn(__fmul_rn(d, mem), c);
        const float v = __fsub_rn(mem, th);
        const float s = (v > 0.0f) ? 1.0f : 0.0f;
        out[idx] = s;
        mem = __fsub_rn(mem, __fmul_rn(s, th));
    }
}

// ---------------------------------------------------------------------------
// Launch: inputs in metadata order: x, W, b, decay, thresh.
// ---------------------------------------------------------------------------
extern "C" void kernel_launch(void* const* d_in, const int* in_sizes, int n_in,
                              void* d_out, int out_size)
{
    const float* x      = (const float*)d_in[0];  // [T, B, C_IN]
    const float* W      = (const float*)d_in[1];  // [C_OUT, C_IN]
    const float* bias   = (const float*)d_in[2];  // [C_OUT]
    const float* decay  = (const float*)d_in[3];  // [1]
    const float* thresh = (const float*)d_in[4];  // [1]
    float* out = (float*)d_out;                   // [T, B, C_OUT]

    float* cur = nullptr;
    cudaGetSymbolAddress((void**)&cur, g_current);

    dim3 gblock(256);
    dim3 ggrid(C_OUT / BN, M_DIM / BM);   // (64, 64)
    gemm_nt_bias_f32x2_kernel<<<ggrid, gblock>>>(x, W, bias, cur);

    const int neurons = BATCH * C_OUT;    // 1,048,576
    lif_scan_kernel<<<neurons / 256, 256>>>(cur, out, decay, thresh);
}

// round 14
// speedup vs baseline: 4.1263x; 1.2095x over previous
#include <cuda_runtime.h>
#include <cstdint>

// Problem shape (fixed by setup_inputs): T=32, B=256, C_in=C_out=4096.
#define T_STEPS 32
#define BATCH   256
#define C_IN    4096
#define C_OUT   4096
#define M_DIM   (T_STEPS * BATCH)   // 8192 GEMM rows

// Scratch for pre-activation currents: [T*B, C_OUT] fp32 = 128 MB.
__device__ float g_current[(size_t)M_DIM * C_OUT];

typedef unsigned long long ull;

// Packed f32x2 ops. Per-component rounding identical to scalar RN ops.
__device__ __forceinline__ ull fma2(ull a, ull b, ull c) {
    ull d;
    asm("fma.rn.f32x2 %0, %1, %2, %3;" : "=l"(d) : "l"(a), "l"(b), "l"(c));
    return d;
}
__device__ __forceinline__ ull add2(ull a, ull b) {
    ull d;
    asm("add.rn.f32x2 %0, %1, %2;" : "=l"(d) : "l"(a), "l"(b));
    return d;
}
__device__ __forceinline__ ull pack2(float lo, float hi) {
    ull d;
    asm("mov.b64 %0, {%1, %2};" : "=l"(d) : "f"(lo), "f"(hi));
    return d;
}
__device__ __forceinline__ void unpack2(ull v, float& lo, float& hi) {
    asm("mov.b64 {%0, %1}, %2;" : "=f"(lo), "=f"(hi) : "l"(v));
}

// ---------------------------------------------------------------------------
// GEMM (NT): C[m][n] = sum_k A[m][k]*W[n][k] + bias[n]
// Arithmetic IDENTICAL to R13 (7373us PASS @ 9.680577e-4): fresh 32-term
// packed-FMA chains per BK=32 slab, plain add2 merge, same epilogue.
// Perf-only changes:
//   * #pragma unroll 8 on the kk loop (hot body ~3.5KB -> L0-I$ resident;
//     full unroll was ~13.8KB, over the 6KB L0).
//   * __launch_bounds__(256, 2): 2 CTAs/SM (96KB smem/SM) so sync/prefetch
//     bubbles on one CTA are covered by the other's FFMA2 stream.
// ---------------------------------------------------------------------------
#define BM 128
#define BN 64
#define BK 32
#define TM 8
#define TN 4

__global__ __launch_bounds__(256, 2)
void gemm_nt_bias_f32x2_kernel(const float* __restrict__ A,
                               const float* __restrict__ W,
                               const float* __restrict__ bias,
                               float* __restrict__ C)
{
    __shared__ float As[2][BK][BM];   // 2 x 16 KB
    __shared__ float Bs[2][BK][BN];   // 2 x  8 KB

    const int K  = C_IN;
    const int m0 = blockIdx.y * BM;
    const int n0 = blockIdx.x * BN;

    const int tid = threadIdx.x;
    const int tx  = tid & 15;      // 16 thread-cols * TN=4  -> 64
    const int ty  = tid >> 4;      // 16 thread-rows * TM=8  -> 128

    // Packed accumulators: [pair-of-m][n], pair ip covers rows (2ip, 2ip+1).
    ull acc[TM / 2][TN];
#pragma unroll
    for (int ip = 0; ip < TM / 2; ip++)
#pragma unroll
        for (int j = 0; j < TN; j++) acc[ip][j] = 0ull;

    // Register staging for global->shared prefetch (same slot plan as R6/R13).
    float4 rA[4], rB[2];

    auto ldg_slab = [&](int k0) {
#pragma unroll
        for (int i = 0; i < 4; i++) {
            const int s   = tid * 4 + i;
            const int row = s >> 3;
            const int q   = s & 7;
            rA[i] = *reinterpret_cast<const float4*>(
                A + (size_t)(m0 + row) * K + k0 + q * 4);
        }
#pragma unroll
        for (int i = 0; i < 2; i++) {
            const int s   = tid * 2 + i;
            const int row = s >> 3;
            const int q   = s & 7;
            rB[i] = *reinterpret_cast<const float4*>(
                W + (size_t)(n0 + row) * K + k0 + q * 4);
        }
    };
    auto sts_slab = [&](int buf) {
#pragma unroll
        for (int i = 0; i < 4; i++) {
            const int s   = tid * 4 + i;
            const int row = s >> 3;
            const int q   = s & 7;
            As[buf][q * 4 + 0][row] = rA[i].x;
            As[buf][q * 4 + 1][row] = rA[i].y;
            As[buf][q * 4 + 2][row] = rA[i].z;
            As[buf][q * 4 + 3][row] = rA[i].w;
        }
#pragma unroll
        for (int i = 0; i < 2; i++) {
            const int s   = tid * 2 + i;
            const int row = s >> 3;
            const int q   = s & 7;
            Bs[buf][q * 4 + 0][row] = rB[i].x;
            Bs[buf][q * 4 + 1][row] = rB[i].y;
            Bs[buf][q * 4 + 2][row] = rB[i].z;
            Bs[buf][q * 4 + 3][row] = rB[i].w;
        }
    };

    // Prologue: stage slab 0.
    ldg_slab(0);
    sts_slab(0);
    __syncthreads();

    int buf = 0;
    for (int k0 = 0; k0 < K; k0 += BK) {
        const bool has_next = (k0 + BK) < K;
        if (has_next) ldg_slab(k0 + BK);   // prefetch next slab into registers

        // Fresh packed slab accumulator (32-term RN-exact FMA chains).
        ull blk[TM / 2][TN];
#pragma unroll
        for (int ip = 0; ip < TM / 2; ip++)
#pragma unroll
            for (int j = 0; j < TN; j++) blk[ip][j] = 0ull;

#pragma unroll 8
        for (int kk = 0; kk < BK; kk++) {
            // A fragment: rows ty*8 .. ty*8+7 as 4 natural f32x2 pairs.
            const ulonglong2 av0 =
                *reinterpret_cast<const ulonglong2*>(&As[buf][kk][ty * TM]);
            const ulonglong2 av1 =
                *reinterpret_cast<const ulonglong2*>(&As[buf][kk][ty * TM + 4]);
            ull ap[4];
            ap[0] = av0.x; ap[1] = av0.y; ap[2] = av1.x; ap[3] = av1.y;

            // B fragment: 4 scalars, duplicated into packed lanes (MOVs on
            // the non-binding pipe — proven free by the R6/R12 A/B test).
            const float4 bv =
                *reinterpret_cast<const float4*>(&Bs[buf][kk][tx * TN]);
            ull bd[4];
            bd[0] = pack2(bv.x, bv.x);
            bd[1] = pack2(bv.y, bv.y);
            bd[2] = pack2(bv.z, bv.z);
            bd[3] = pack2(bv.w, bv.w);

#pragma unroll
            for (int ip = 0; ip < TM / 2; ip++)
#pragma unroll
                for (int j = 0; j < TN; j++)
                    blk[ip][j] = fma2(ap[ip], bd[j], blk[ip][j]);
        }

        // Plain merge: one packed add per accumulator per slab (irreducible).
#pragma unroll
        for (int ip = 0; ip < TM / 2; ip++)
#pragma unroll
            for (int j = 0; j < TN; j++)
                acc[ip][j] = add2(acc[ip][j], blk[ip][j]);

        if (has_next) {
            sts_slab(buf ^ 1);   // fill the idle buffer
            __syncthreads();
            buf ^= 1;
        }
    }

    // Epilogue: add bias, store fp32 currents (same exprs as R13).
#pragma unroll
    for (int ip = 0; ip < TM / 2; ip++) {
        float a_lo[TN], a_hi[TN];
#pragma unroll
        for (int j = 0; j < TN; j++)
            unpack2(acc[ip][j], a_lo[j], a_hi[j]);
        const int n = n0 + tx * TN;
        {
            const int m = m0 + ty * TM + 2 * ip;
            float4 v;
            v.x = __fadd_rn(a_lo[0], bias[n + 0]);
            v.y = __fadd_rn(a_lo[1], bias[n + 1]);
            v.z = __fadd_rn(a_lo[2], bias[n + 2]);
            v.w = __fadd_rn(a_lo[3], bias[n + 3]);
            *reinterpret_cast<float4*>(C + (size_t)m * C_OUT + n) = v;
        }
        {
            const int m = m0 + ty * TM + 2 * ip + 1;
            float4 v;
            v.x = __fadd_rn(a_hi[0], bias[n + 0]);
            v.y = __fadd_rn(a_hi[1], bias[n + 1]);
            v.z = __fadd_rn(a_hi[2], bias[n + 2]);
            v.w = __fadd_rn(a_hi[3], bias[n + 3]);
            *reinterpret_cast<float4*>(C + (size_t)m * C_OUT + n) = v;
        }
    }
}

// ---------------------------------------------------------------------------
// LIF scan (identical numerics and form to the passing R5 kernel, 38.9us).
// ---------------------------------------------------------------------------
__global__ __launch_bounds__(256)
void lif_scan_kernel(const float* __restrict__ cur,
                     float* __restrict__ out,
                     const float* __restrict__ decay,
                     const float* __restrict__ thresh)
{
    const int i = blockIdx.x * blockDim.x + threadIdx.x;
    const float d  = decay[0];
    const float th = thresh[0];
    const size_t stride = (size_t)BATCH * C_OUT;

    float mem = 0.0f;
#pragma unroll
    for (int t = 0; t < T_STEPS; t++) {
        const size_t idx = (size_t)t * stride + i;
        const float c = cur[idx];
        mem = __fadd_rn(__fmul_rn(d, mem), c);
        const float v = __fsub_rn(mem, th);
        const float s = (v > 0.0f) ? 1.0f : 0.0f;
        out[idx] = s;
        mem = __fsub_rn(mem, __fmul_rn(s, th));
    }
}

// ---------------------------------------------------------------------------
// Launch: inputs in metadata order: x, W, b, decay, thresh.
// ---------------------------------------------------------------------------
extern "C" void kernel_launch(void* const* d_in, const int* in_sizes, int n_in,
                              void* d_out, int out_size)
{
    const float* x      = (const float*)d_in[0];  // [T, B, C_IN]
    const float* W      = (const float*)d_in[1];  // [C_OUT, C_IN]
    const float* bias   = (const float*)d_in[2];  // [C_OUT]
    const float* decay  = (const float*)d_in[3];  // [1]
    const float* thresh = (const float*)d_in[4];  // [1]
    float* out = (float*)d_out;                   // [T, B, C_OUT]

    float* cur = nullptr;
    cudaGetSymbolAddress((void**)&cur, g_current);

    dim3 gblock(256);
    dim3 ggrid(C_OUT / BN, M_DIM / BM);   // (64, 64)
    gemm_nt_bias_f32x2_kernel<<<ggrid, gblock>>>(x, W, bias, cur);

    const int neurons = BATCH * C_OUT;    // 1,048,576
    lif_scan_kernel<<<neurons / 256, 256>>>(cur, out, decay, thresh);
}